// round 1
// baseline (speedup 1.0000x reference)
#include <cuda_runtime.h>

// VectorQuant: N=8, S=2048, C=4, K=512, V=64
// d_out layout: [out0: 8*2048*4*64][out1: 8*2048*4][out2: 8*2048*4]

#define NS  16384   // N*S rows
#define CC  4
#define KK  512
#define VV  64
#define TPB 256

__device__ __forceinline__ unsigned long long ffma2(unsigned long long a,
                                                    unsigned long long b,
                                                    unsigned long long c) {
    unsigned long long d;
    asm("fma.rn.f32x2 %0, %1, %2, %3;" : "=l"(d) : "l"(a), "l"(b), "l"(c));
    return d;
}

__device__ __forceinline__ float2 unpack2(unsigned long long u) {
    float2 f;
    asm("mov.b64 {%0, %1}, %2;" : "=f"(f.x), "=f"(f.y) : "l"(u));
    return f;
}

extern __shared__ float smem_dyn[];

__global__ void __launch_bounds__(TPB, 1)
vq_kernel(const float* __restrict__ x, const float* __restrict__ emb,
          float* __restrict__ out0, float* __restrict__ out1,
          float* __restrict__ out2)
{
    float* se  = smem_dyn;            // KK*VV floats (128 KB), embedding for this c
    float* se2 = smem_dyn + KK * VV;  // KK floats, ||e_k||^2

    const int c = blockIdx.y;
    const float* ec = emb + (size_t)c * KK * VV;

    // Cooperative load of embedding[c] into smem (coalesced float4)
    {
        const float4* ec4 = (const float4*)ec;
        float4* se4 = (float4*)se;
        #pragma unroll
        for (int i = 0; i < (KK * VV / 4) / TPB; i++)
            se4[threadIdx.x + i * TPB] = ec4[threadIdx.x + i * TPB];
    }
    // ||e_k||^2 computed from global (L2-hot), 2 rows per thread
    #pragma unroll
    for (int j = 0; j < KK / TPB; j++) {
        int k = threadIdx.x + j * TPB;
        const float4* row = (const float4*)(ec + (size_t)k * VV);
        float s = 0.f;
        #pragma unroll
        for (int i = 0; i < VV / 4; i++) {
            float4 v = row[i];
            s += v.x * v.x + v.y * v.y + v.z * v.z + v.w * v.w;
        }
        se2[k] = s;
    }
    __syncthreads();

    // One row per thread, kept in registers as 32 packed f32x2
    const int r = blockIdx.x * TPB + threadIdx.x;
    const float* xrow = x + ((size_t)r * CC + c) * VV;
    unsigned long long xr[VV / 2];
    {
        const ulonglong2* xp = (const ulonglong2*)xrow;
        #pragma unroll
        for (int i = 0; i < VV / 4; i++) {
            ulonglong2 t = xp[i];
            xr[2 * i]     = t.x;
            xr[2 * i + 1] = t.y;
        }
    }

    // Argmin over k of (||e||^2 - 2 x.e); x^2 term is constant per row.
    // All lanes read the same smem address -> broadcast, conflict-free.
    float best = 3.4e38f;
    int bestk = 0;
    for (int k = 0; k < KK; k++) {
        const ulonglong2* erow = (const ulonglong2*)(se + (size_t)k * VV);
        unsigned long long a0 = 0ull, a1 = 0ull;  // bit pattern 0 == (0.f, 0.f)
        #pragma unroll
        for (int i = 0; i < VV / 4; i++) {
            ulonglong2 e = erow[i];
            a0 = ffma2(xr[2 * i],     e.x, a0);
            a1 = ffma2(xr[2 * i + 1], e.y, a1);
        }
        float2 f0 = unpack2(a0);
        float2 f1 = unpack2(a1);
        float dot = (f0.x + f0.y) + (f1.x + f1.y);
        float d = se2[k] - 2.0f * dot;
        if (d < best) { best = d; bestk = k; }   // strict <: first-index ties like jnp.argmin
    }

    // Epilogue: out0 = embedding row; out1 = out2 = sum((x - e)^2)
    const float4* eb = (const float4*)(se + (size_t)bestk * VV);
    float4* o0 = (float4*)(out0 + ((size_t)r * CC + c) * VV);
    float ss = 0.f;
    #pragma unroll
    for (int i = 0; i < VV / 4; i++) {
        float4 ev = eb[i];
        float2 xa = unpack2(xr[2 * i]);
        float2 xb = unpack2(xr[2 * i + 1]);
        float d0 = xa.x - ev.x;
        float d1 = xa.y - ev.y;
        float d2 = xb.x - ev.z;
        float d3 = xb.y - ev.w;
        ss += d0 * d0 + d1 * d1 + d2 * d2 + d3 * d3;
        o0[i] = ev;
    }
    out1[(size_t)r * CC + c] = ss;
    out2[(size_t)r * CC + c] = ss;
}

extern "C" void kernel_launch(void* const* d_in, const int* in_sizes, int n_in,
                              void* d_out, int out_size) {
    const float* x   = (const float*)d_in[0];
    const float* emb = (const float*)d_in[1];
    float* out  = (float*)d_out;
    float* out0 = out;
    float* out1 = out + (size_t)NS * CC * VV;
    float* out2 = out1 + (size_t)NS * CC;

    size_t smem = (size_t)(KK * VV + KK) * sizeof(float);
    cudaFuncSetAttribute(vq_kernel, cudaFuncAttributeMaxDynamicSharedMemorySize,
                         (int)smem);
    dim3 grid(NS / TPB, CC);
    vq_kernel<<<grid, TPB, smem>>>(x, emb, out0, out1, out2);
}

// round 2
// speedup vs baseline: 1.0661x; 1.0661x over previous
#include <cuda_runtime.h>

// VectorQuant: N=8, S=2048, C=4, K=512, V=64
// d_out layout: [out0: 8*2048*4*64][out1: 8*2048*4][out2: 8*2048*4]

#define NS  16384   // N*S rows
#define CC  4
#define KK  512
#define VV  64
#define TPB 512

__device__ __forceinline__ unsigned long long ffma2(unsigned long long a,
                                                    unsigned long long b,
                                                    unsigned long long c) {
    unsigned long long d;
    asm("fma.rn.f32x2 %0, %1, %2, %3;" : "=l"(d) : "l"(a), "l"(b), "l"(c));
    return d;
}

__device__ __forceinline__ unsigned long long fadd2(unsigned long long a,
                                                    unsigned long long b) {
    unsigned long long d;
    asm("add.rn.f32x2 %0, %1, %2;" : "=l"(d) : "l"(a), "l"(b));
    return d;
}

__device__ __forceinline__ float2 unpack2(unsigned long long u) {
    float2 f;
    asm("mov.b64 {%0, %1}, %2;" : "=f"(f.x), "=f"(f.y) : "l"(u));
    return f;
}

__device__ __forceinline__ unsigned long long pack2(float lo, float hi) {
    unsigned long long u;
    asm("mov.b64 %0, {%1, %2};" : "=l"(u) : "f"(lo), "f"(hi));
    return u;
}

extern __shared__ float smem_dyn[];

__global__ void __launch_bounds__(TPB, 1)
vq_kernel(const float* __restrict__ x, const float* __restrict__ emb,
          float* __restrict__ out0, float* __restrict__ out1,
          float* __restrict__ out2)
{
    float* se  = smem_dyn;            // KK*VV floats (128 KB), embedding for this c
    float* se2 = smem_dyn + KK * VV;  // KK floats, ||e_k||^2

    const int c = blockIdx.y;
    const float* ec = emb + (size_t)c * KK * VV;

    // Cooperative load of embedding[c] into smem (coalesced float4)
    {
        const float4* ec4 = (const float4*)ec;
        float4* se4 = (float4*)se;
        #pragma unroll
        for (int i = 0; i < (KK * VV / 4) / TPB; i++)
            se4[threadIdx.x + i * TPB] = ec4[threadIdx.x + i * TPB];
    }
    // ||e_k||^2 from global (L2-hot), one row per thread for k = tid (<512)
    {
        int k = threadIdx.x;
        const float4* row = (const float4*)(ec + (size_t)k * VV);
        float s = 0.f;
        #pragma unroll
        for (int i = 0; i < VV / 4; i++) {
            float4 v = row[i];
            s += v.x * v.x + v.y * v.y + v.z * v.z + v.w * v.w;
        }
        se2[k] = s;
    }
    __syncthreads();

    // One row per thread; keep (-2*x) in registers as 32 packed f32x2 so the
    // accumulated value is directly  -2*x.e ; seed with ||e||^2 -> d2 (+const).
    const int r = blockIdx.x * TPB + threadIdx.x;
    const float* xrow = x + ((size_t)r * CC + c) * VV;
    unsigned long long xr[VV / 2];
    {
        const float4* xp = (const float4*)xrow;
        #pragma unroll
        for (int i = 0; i < VV / 4; i++) {
            float4 t = xp[i];
            xr[2 * i]     = pack2(-2.0f * t.x, -2.0f * t.y);
            xr[2 * i + 1] = pack2(-2.0f * t.z, -2.0f * t.w);
        }
    }

    float best = 3.4e38f;
    int bestk = 0;
    #pragma unroll 2
    for (int k = 0; k < KK; k++) {
        const ulonglong2* erow = (const ulonglong2*)(se + (size_t)k * VV);
        // 4 accumulators: chain length 8 per accumulator
        unsigned long long a0 = pack2(se2[k], 0.f);
        unsigned long long a1 = 0ull, a2 = 0ull, a3 = 0ull;
        #pragma unroll
        for (int i = 0; i < VV / 8; i++) {
            ulonglong2 e0 = erow[2 * i];
            ulonglong2 e1 = erow[2 * i + 1];
            a0 = ffma2(xr[4 * i],     e0.x, a0);
            a1 = ffma2(xr[4 * i + 1], e0.y, a1);
            a2 = ffma2(xr[4 * i + 2], e1.x, a2);
            a3 = ffma2(xr[4 * i + 3], e1.y, a3);
        }
        a0 = fadd2(a0, a1);
        a2 = fadd2(a2, a3);
        a0 = fadd2(a0, a2);
        float2 f = unpack2(a0);
        float d = f.x + f.y;   // = ||e||^2 - 2 x.e
        if (d < best) { best = d; bestk = k; }   // strict <: first-index ties
    }

    // Epilogue: out0 = embedding row; out1 = out2 = sum((x - e)^2)
    const float4* eb = (const float4*)(se + (size_t)bestk * VV);
    float4* o0 = (float4*)(out0 + ((size_t)r * CC + c) * VV);
    float ss = 0.f;
    #pragma unroll
    for (int i = 0; i < VV / 4; i++) {
        float4 ev = eb[i];
        float2 xa = unpack2(xr[2 * i]);      // = -2x
        float2 xb = unpack2(xr[2 * i + 1]);
        float d0 = -0.5f * xa.x - ev.x;
        float d1 = -0.5f * xa.y - ev.y;
        float d2 = -0.5f * xb.x - ev.z;
        float d3 = -0.5f * xb.y - ev.w;
        ss += d0 * d0 + d1 * d1 + d2 * d2 + d3 * d3;
        o0[i] = ev;
    }
    out1[(size_t)r * CC + c] = ss;
    out2[(size_t)r * CC + c] = ss;
}

extern "C" void kernel_launch(void* const* d_in, const int* in_sizes, int n_in,
                              void* d_out, int out_size) {
    const float* x   = (const float*)d_in[0];
    const float* emb = (const float*)d_in[1];
    float* out  = (float*)d_out;
    float* out0 = out;
    float* out1 = out + (size_t)NS * CC * VV;
    float* out2 = out1 + (size_t)NS * CC;

    size_t smem = (size_t)(KK * VV + KK) * sizeof(float);
    cudaFuncSetAttribute(vq_kernel, cudaFuncAttributeMaxDynamicSharedMemorySize,
                         (int)smem);
    dim3 grid(NS / TPB, CC);
    vq_kernel<<<grid, TPB, smem>>>(x, emb, out0, out1, out2);
}

// round 4
// speedup vs baseline: 1.3432x; 1.2599x over previous
#include <cuda_runtime.h>

// VectorQuant: N=8, S=2048, C=4, K=512, V=64
// d_out layout: [out0: 8*2048*4*64][out1: 8*2048*4][out2: 8*2048*4]

#define NS  16384   // N*S rows
#define CC  4
#define KK  512
#define VV  64
#define TPB 256
#define RPT 2       // rows per thread

__device__ __forceinline__ unsigned long long ffma2(unsigned long long a,
                                                    unsigned long long b,
                                                    unsigned long long c) {
    unsigned long long d;
    asm("fma.rn.f32x2 %0, %1, %2, %3;" : "=l"(d) : "l"(a), "l"(b), "l"(c));
    return d;
}

__device__ __forceinline__ unsigned long long fadd2(unsigned long long a,
                                                    unsigned long long b) {
    unsigned long long d;
    asm("add.rn.f32x2 %0, %1, %2;" : "=l"(d) : "l"(a), "l"(b));
    return d;
}

__device__ __forceinline__ float2 unpack2(unsigned long long u) {
    float2 f;
    asm("mov.b64 {%0, %1}, %2;" : "=f"(f.x), "=f"(f.y) : "l"(u));
    return f;
}

__device__ __forceinline__ unsigned long long pack2(float lo, float hi) {
    unsigned long long u;
    asm("mov.b64 %0, {%1, %2};" : "=l"(u) : "f"(lo), "f"(hi));
    return u;
}

extern __shared__ float smem_dyn[];

__global__ void __launch_bounds__(TPB, 1)
vq_kernel(const float* __restrict__ x, const float* __restrict__ emb,
          float* __restrict__ out0, float* __restrict__ out1,
          float* __restrict__ out2)
{
    float* se  = smem_dyn;            // KK*VV floats (128 KB), embedding for this c
    float* se2 = smem_dyn + KK * VV;  // KK floats, ||e_k||^2

    const int c = blockIdx.y;
    const float* ec = emb + (size_t)c * KK * VV;

    // Cooperative load of embedding[c] into smem (coalesced float4)
    {
        const float4* ec4 = (const float4*)ec;
        float4* se4 = (float4*)se;
        #pragma unroll
        for (int i = 0; i < (KK * VV / 4) / TPB; i++)
            se4[threadIdx.x + i * TPB] = ec4[threadIdx.x + i * TPB];
    }
    // ||e_k||^2 from global (L2-hot)
    #pragma unroll
    for (int j = 0; j < KK / TPB; j++) {
        int k = threadIdx.x + j * TPB;
        const float4* row = (const float4*)(ec + (size_t)k * VV);
        float s = 0.f;
        #pragma unroll
        for (int i = 0; i < VV / 4; i++) {
            float4 v = row[i];
            s += v.x * v.x + v.y * v.y + v.z * v.z + v.w * v.w;
        }
        se2[k] = s;
    }
    __syncthreads();

    // Two rows per thread; keep (-2*x) in registers as packed f32x2.
    // Every LDS broadcast of an embedding row is reused by both rows.
    const int r0 = blockIdx.x * (TPB * RPT) + threadIdx.x;  // row 0
    const int r1 = r0 + TPB;                                // row 1
    unsigned long long xr0[VV / 2], xr1[VV / 2];
    {
        const float4* xp0 = (const float4*)(x + ((size_t)r0 * CC + c) * VV);
        const float4* xp1 = (const float4*)(x + ((size_t)r1 * CC + c) * VV);
        #pragma unroll
        for (int i = 0; i < VV / 4; i++) {
            float4 t0 = xp0[i];
            float4 t1 = xp1[i];
            xr0[2 * i]     = pack2(-2.0f * t0.x, -2.0f * t0.y);
            xr0[2 * i + 1] = pack2(-2.0f * t0.z, -2.0f * t0.w);
            xr1[2 * i]     = pack2(-2.0f * t1.x, -2.0f * t1.y);
            xr1[2 * i + 1] = pack2(-2.0f * t1.z, -2.0f * t1.w);
        }
    }

    float best0 = 3.4e38f, best1 = 3.4e38f;
    int bestk0 = 0, bestk1 = 0;
    #pragma unroll 2
    for (int k = 0; k < KK; k++) {
        const ulonglong2* erow = (const ulonglong2*)(se + (size_t)k * VV);
        unsigned long long a0 = 0ull, a1 = 0ull, a2 = 0ull, a3 = 0ull;  // row 0
        unsigned long long b0 = 0ull, b1 = 0ull, b2 = 0ull, b3 = 0ull;  // row 1
        #pragma unroll
        for (int i = 0; i < VV / 8; i++) {
            ulonglong2 e0 = erow[2 * i];
            ulonglong2 e1 = erow[2 * i + 1];
            a0 = ffma2(xr0[4 * i],     e0.x, a0);
            b0 = ffma2(xr1[4 * i],     e0.x, b0);
            a1 = ffma2(xr0[4 * i + 1], e0.y, a1);
            b1 = ffma2(xr1[4 * i + 1], e0.y, b1);
            a2 = ffma2(xr0[4 * i + 2], e1.x, a2);
            b2 = ffma2(xr1[4 * i + 2], e1.x, b2);
            a3 = ffma2(xr0[4 * i + 3], e1.y, a3);
            b3 = ffma2(xr1[4 * i + 3], e1.y, b3);
        }
        float e2k = se2[k];
        a0 = fadd2(a0, a1); a2 = fadd2(a2, a3); a0 = fadd2(a0, a2);
        b0 = fadd2(b0, b1); b2 = fadd2(b2, b3); b0 = fadd2(b0, b2);
        float2 fa = unpack2(a0);
        float2 fb = unpack2(b0);
        float d0 = e2k + fa.x + fa.y;   // = ||e||^2 - 2 x0.e
        float d1 = e2k + fb.x + fb.y;   // = ||e||^2 - 2 x1.e
        if (d0 < best0) { best0 = d0; bestk0 = k; }   // strict <: first-index ties
        if (d1 < best1) { best1 = d1; bestk1 = k; }
    }

    // Epilogue: out0 = embedding row; out1 = out2 = sum((x - e)^2)
    #pragma unroll
    for (int rr = 0; rr < RPT; rr++) {
        const int r = rr ? r1 : r0;
        const int bk = rr ? bestk1 : bestk0;
        const unsigned long long* xr = rr ? xr1 : xr0;
        const float4* eb = (const float4*)(se + (size_t)bk * VV);
        float4* o0 = (float4*)(out0 + ((size_t)r * CC + c) * VV);
        float ss = 0.f;
        #pragma unroll
        for (int i = 0; i < VV / 4; i++) {
            float4 ev = eb[i];
            float2 xa = unpack2(xr[2 * i]);      // = -2x
            float2 xb = unpack2(xr[2 * i + 1]);
            float d0 = -0.5f * xa.x - ev.x;
            float d1 = -0.5f * xa.y - ev.y;
            float d2 = -0.5f * xb.x - ev.z;
            float d3 = -0.5f * xb.y - ev.w;
            ss += d0 * d0 + d1 * d1 + d2 * d2 + d3 * d3;
            o0[i] = ev;
        }
        out1[(size_t)r * CC + c] = ss;
        out2[(size_t)r * CC + c] = ss;
    }
}

extern "C" void kernel_launch(void* const* d_in, const int* in_sizes, int n_in,
                              void* d_out, int out_size) {
    const float* x   = (const float*)d_in[0];
    const float* emb = (const float*)d_in[1];
    float* out  = (float*)d_out;
    float* out0 = out;
    float* out1 = out + (size_t)NS * CC * VV;
    float* out2 = out1 + (size_t)NS * CC;

    size_t smem = (size_t)(KK * VV + KK) * sizeof(float);
    cudaFuncSetAttribute(vq_kernel, cudaFuncAttributeMaxDynamicSharedMemorySize,
                         (int)smem);
    dim3 grid(NS / (TPB * RPT), CC);
    vq_kernel<<<grid, TPB, smem>>>(x, emb, out0, out1, out2);
}